// round 2
// baseline (speedup 1.0000x reference)
#include <cuda_runtime.h>
#include <float.h>

#define S_TILE   128
#define K_CHUNK  128
#define NTILES   1024          // (32*64*64)/128
#define GRID_MAIN 304          // 152 SMs x 2 CTAs, persistent + work-steal
#define SMEM_BYTES (2*64*128*4 + 128*4 + 128*4)   // 66560

typedef unsigned long long u64;

__device__ float  g_cbT[64 * 1024];   // [c][k]
__device__ float  g_esq[1024];
__device__ double g_part[NTILES];
__device__ int    g_tile;

__device__ __forceinline__ u64 splat2(float v) {
    u64 r; asm("mov.b64 %0, {%1, %1};" : "=l"(r) : "f"(v)); return r;
}
__device__ __forceinline__ void ffma2(u64& d, u64 a, u64 b) {
    asm("fma.rn.f32x2 %0, %1, %2, %0;" : "+l"(d) : "l"(a), "l"(b));
}
__device__ __forceinline__ float2 unpack2(u64 p) {
    float2 f; asm("mov.b64 {%0, %1}, %2;" : "=f"(f.x), "=f"(f.y) : "l"(p));
    return f;
}

// Transpose codebook -> [c][k] (coalesced writes, L2-absorbed scattered reads)
// and precompute e_sq (square-then-add, matching jnp.sum(cb*cb, axis=1)).
// Also resets the work-steal counter.
__global__ void vq_prep(const float* __restrict__ cb) {
    int o = blockIdx.x * 256 + threadIdx.x;
    if (o == 0) g_tile = 0;
    if (o < 65536) {
        int c = o >> 10, k = o & 1023;
        g_cbT[o] = __ldg(cb + k * 64 + c);
    }
    if (o < 1024) {
        const float* row = cb + o * 64;
        float s = 0.f;
        #pragma unroll
        for (int c = 0; c < 64; ++c)
            s = __fadd_rn(s, __fmul_rn(row[c], row[c]));
        g_esq[o] = s;
    }
}

__global__ void __launch_bounds__(256, 2)
vq_main(const float* __restrict__ x, const float* __restrict__ cb,
        float* __restrict__ out) {
    extern __shared__ float smem[];
    float* xs     = smem;                  // [64][128] x tile, c-major
    float* es     = smem + 8192;           // [64][128] codebook chunk, c-major
    float* xsq_sh = smem + 16384;          // [128]
    int*   idx_sh = (int*)(smem + 16512);  // [128]
    float* rmv    = es;                    // reuse es after mainloop: [16][128]
    int*   rmk    = (int*)(es + 2048);     // [16][128]
    __shared__ int s_tile;

    const int tid = threadIdx.x;
    const int tx  = tid & 15;     // spatial group
    const int ty  = tid >> 4;     // code group

    while (true) {
        if (tid == 0) s_tile = atomicAdd(&g_tile, 1);
        __syncthreads();
        const int tileId = s_tile;
        if (tileId >= NTILES) return;

        const int R   = tileId * S_TILE;
        const int b   = R >> 12;
        const int sb  = R & 4095;
        const float* xbase = x + (size_t)b * 262144 + sb;

        // Load x tile: 64 channels x 128 spatial (contiguous per channel)
        #pragma unroll
        for (int i = 0; i < 8; ++i) {
            int lin = i * 256 + tid;
            int c   = lin >> 5;
            int f4  = (lin & 31) << 2;
            *(float4*)(xs + c * 128 + f4) =
                *(const float4*)(xbase + (size_t)c * 4096 + f4);
        }
        __syncthreads();

        // x_sq per spatial row: sequential over c, square-then-add (ref order)
        if (tid < 128) {
            float s = 0.f;
            #pragma unroll
            for (int c = 0; c < 64; ++c) {
                float v = xs[c * 128 + tid];
                s = __fadd_rn(s, __fmul_rn(v, v));
            }
            xsq_sh[tid] = s;
        }
        __syncthreads();

        float xsq[8];
        #pragma unroll
        for (int i = 0; i < 8; ++i) {
            int sl = (i < 4) ? (tx * 4 + i) : (64 + tx * 4 + i - 4);
            xsq[i] = xsq_sh[sl];
        }

        float minv[8]; int mink[8];
        #pragma unroll
        for (int i = 0; i < 8; ++i) { minv[i] = FLT_MAX; mink[i] = 0; }

        for (int chunk = 0; chunk < 8; ++chunk) {
            const int k0 = chunk * K_CHUNK;
            // Load codebook chunk from transposed copy (conflict-free)
            #pragma unroll
            for (int i = 0; i < 8; ++i) {
                int lin = i * 256 + tid;
                int c   = lin >> 5;
                int f4  = (lin & 31) << 2;
                *(float4*)(es + c * 128 + f4) =
                    *(const float4*)(g_cbT + c * 1024 + k0 + f4);
            }
            __syncthreads();

            // acc2[i2][j]: packed f32x2 pairs along spatial dim
            u64 acc2[4][8];
            #pragma unroll
            for (int i2 = 0; i2 < 4; ++i2)
                #pragma unroll
                for (int j = 0; j < 8; ++j) acc2[i2][j] = 0ull;

            #pragma unroll 4
            for (int c = 0; c < 64; ++c) {
                u64 a2[4];
                *(ulonglong2*)(a2)     = *(ulonglong2*)(xs + c * 128 + tx * 4);
                *(ulonglong2*)(a2 + 2) = *(ulonglong2*)(xs + c * 128 + 64 + tx * 4);
                float4 b0 = *(float4*)(es + c * 128 + ty * 4);
                float4 b1 = *(float4*)(es + c * 128 + 64 + ty * 4);
                u64 bb2[8];
                bb2[0] = splat2(b0.x); bb2[1] = splat2(b0.y);
                bb2[2] = splat2(b0.z); bb2[3] = splat2(b0.w);
                bb2[4] = splat2(b1.x); bb2[5] = splat2(b1.y);
                bb2[6] = splat2(b1.z); bb2[7] = splat2(b1.w);
                #pragma unroll
                for (int i2 = 0; i2 < 4; ++i2)
                    #pragma unroll
                    for (int j = 0; j < 8; ++j)
                        ffma2(acc2[i2][j], a2[i2], bb2[j]);
            }

            // Score: d2 = (x_sq + e_sq) - 2*dot, exact rounding order of ref
            #pragma unroll
            for (int j = 0; j < 8; ++j) {
                int kl = (j < 4) ? (ty * 4 + j) : (64 + ty * 4 + j - 4);
                int kg = k0 + kl;                 // strictly increasing
                float esq = __ldg(g_esq + kg);
                #pragma unroll
                for (int i2 = 0; i2 < 4; ++i2) {
                    float2 dp = unpack2(acc2[i2][j]);
                    float t1 = __fadd_rn(xsq[2 * i2], esq);
                    float d2 = __fsub_rn(t1, __fmul_rn(2.0f, dp.x));
                    if (d2 < minv[2 * i2]) { minv[2 * i2] = d2; mink[2 * i2] = kg; }
                    t1 = __fadd_rn(xsq[2 * i2 + 1], esq);
                    d2 = __fsub_rn(t1, __fmul_rn(2.0f, dp.y));
                    if (d2 < minv[2 * i2 + 1]) { minv[2 * i2 + 1] = d2; mink[2 * i2 + 1] = kg; }
                }
            }
            __syncthreads();   // protects es before next chunk load / rmv reuse
        }

        // Cross-thread argmin reduction (16 code-groups per spatial row)
        #pragma unroll
        for (int i = 0; i < 8; ++i) {
            int sl = (i < 4) ? (tx * 4 + i) : (64 + tx * 4 + i - 4);
            rmv[ty * 128 + sl] = minv[i];
            rmk[ty * 128 + sl] = mink[i];
        }
        __syncthreads();
        if (tid < 128) {
            float bv = rmv[tid]; int bk = rmk[tid];
            #pragma unroll
            for (int t = 1; t < 16; ++t) {
                float v = rmv[t * 128 + tid];
                int  k  = rmk[t * 128 + tid];
                if (v < bv || (v == bv && k < bk)) { bv = v; bk = k; }
            }
            idx_sh[tid] = bk;
        }
        __syncthreads();

        // Epilogue: gather codebook rows, write z_q (coalesced per channel),
        // accumulate squared diff deterministically.
        float fsum = 0.f;
        const size_t obase = (size_t)b * 262144 + sb;
        #pragma unroll
        for (int it = 0; it < 32; ++it) {
            int lin = it * 256 + tid;
            int c   = lin >> 7;
            int s   = lin & 127;
            float q = __ldg(cb + idx_sh[s] * 64 + c);
            out[obase + (size_t)c * 4096 + s] = q;
            float d = xs[c * 128 + s] - q;
            fsum = __fmaf_rn(d, d, fsum);
        }
        __syncthreads();
        rmv[tid] = fsum;
        __syncthreads();
        for (int off = 128; off > 0; off >>= 1) {
            if (tid < off) rmv[tid] = __fadd_rn(rmv[tid], rmv[tid + off]);
            __syncthreads();
        }
        if (tid == 0) g_part[tileId] = (double)rmv[0];
        __syncthreads();   // everyone done with smem before next tile steal
    }
}

__global__ void vq_loss(float* loss_out) {
    __shared__ double sh[256];
    double s = 0.0;
    for (int i = threadIdx.x; i < NTILES; i += 256) s += g_part[i];
    sh[threadIdx.x] = s;
    __syncthreads();
    for (int off = 128; off > 0; off >>= 1) {
        if (threadIdx.x < off) sh[threadIdx.x] += sh[threadIdx.x + off];
        __syncthreads();
    }
    if (threadIdx.x == 0) {
        float m = (float)(sh[0] / 8388608.0);
        loss_out[0] = __fadd_rn(m, __fmul_rn(0.25f, m));  // mse + 0.25*mse
    }
}

extern "C" void kernel_launch(void* const* d_in, const int* in_sizes, int n_in,
                              void* d_out, int out_size) {
    const float* x  = (const float*)d_in[0];
    const float* cb = (const float*)d_in[1];
    float* out = (float*)d_out;

    cudaFuncSetAttribute(vq_main, cudaFuncAttributeMaxDynamicSharedMemorySize,
                         SMEM_BYTES);
    vq_prep<<<256, 256>>>(cb);
    vq_main<<<GRID_MAIN, 256, SMEM_BYTES>>>(x, cb, out);
    vq_loss<<<1, 256>>>(out + (out_size - 1));
}

// round 5
// speedup vs baseline: 1.0155x; 1.0155x over previous
#include <cuda_runtime.h>
#include <float.h>

#define S_TILE    128
#define K_CHUNK   256
#define N_CHUNKS  4
#define NTILES    1024          // (32*64*64)/128
#define GRID_MAIN 152           // persistent, 1 CTA/SM, work-steal
// smem floats: xs 8192 | es 2x16384 | xsq 128 | idx 128
#define XS_OFF   0
#define ES_OFF   8192
#define XSQ_OFF  (8192 + 32768)
#define IDX_OFF  (XSQ_OFF + 128)
#define SMEM_BYTES ((IDX_OFF + 128) * 4)   // 164864

__device__ float  g_cbT[64 * 1024];   // [c][k]
__device__ float  g_esq[1024];
__device__ double g_part[NTILES];
__device__ int    g_tile;

__device__ __forceinline__ void cp16(unsigned dst, const float* src) {
    asm volatile("cp.async.cg.shared.global [%0], [%1], 16;\n"
                 :: "r"(dst), "l"(src));
}
__device__ __forceinline__ void cp_commit() {
    asm volatile("cp.async.commit_group;\n");
}
template <int N> __device__ __forceinline__ void cp_wait() {
    asm volatile("cp.async.wait_group %0;\n" :: "n"(N));
}

// Transpose codebook -> [c][k], precompute e_sq (square-then-add, matching
// jnp.sum(cb*cb, axis=1)), reset work-steal counter.
__global__ void vq_prep(const float* __restrict__ cb) {
    int o = blockIdx.x * 256 + threadIdx.x;
    if (o == 0) g_tile = 0;
    if (o < 65536) {
        int c = o >> 10, k = o & 1023;
        g_cbT[o] = __ldg(cb + k * 64 + c);
    }
    if (o < 1024) {
        const float* row = cb + o * 64;
        float s = 0.f;
        #pragma unroll
        for (int c = 0; c < 64; ++c)
            s = __fadd_rn(s, __fmul_rn(row[c], row[c]));
        g_esq[o] = s;
    }
}

__global__ void __launch_bounds__(256, 1)
vq_main(const float* __restrict__ x, const float* __restrict__ cb,
        float* __restrict__ out) {
    extern __shared__ float smem[];
    float* xs     = smem + XS_OFF;         // [64][128] x tile, c-major
    float* xsq_sh = smem + XSQ_OFF;        // [128]
    int*   idx_sh = (int*)(smem + IDX_OFF);
    float* rmv    = smem + ES_OFF;         // staging reuse: [16][128]
    int*   rmk    = (int*)(smem + ES_OFF + 2048);
    __shared__ int s_tile;

    const int tid = threadIdx.x;
    const int tx  = tid & 15;     // 16 spatial groups x 8 rows
    const int ty  = tid >> 4;     // 16 code groups x 16 codes
    const unsigned smem_u32 = (unsigned)__cvta_generic_to_shared(smem);

    while (true) {
        if (tid == 0) s_tile = atomicAdd(&g_tile, 1);
        __syncthreads();             // also fences prev tile's smem use
        const int tileId = s_tile;
        if (tileId >= NTILES) return;

        const int b  = tileId >> 5;          // 32 tiles per batch image
        const int sb = (tileId & 31) * S_TILE;
        const float* xbase = x + (size_t)b * 262144 + sb;

        // --- async load x tile (group 0): 64 ch x 128 sp, 8 x 16B per thread
        #pragma unroll
        for (int i = 0; i < 8; ++i) {
            int lin = i * 256 + tid;          // 2048 16B-chunks
            int c   = lin >> 5;
            int f4  = (lin & 31) << 2;
            cp16(smem_u32 + (XS_OFF + c * 128 + f4) * 4,
                 xbase + (size_t)c * 4096 + f4);
        }
        cp_commit();
        // --- async load es chunk 0 into buf0 (group 1)
        #pragma unroll
        for (int i = 0; i < 16; ++i) {
            int lin = i * 256 + tid;          // 4096 16B-chunks
            int c   = lin >> 6;
            int k4  = (lin & 63) << 2;
            cp16(smem_u32 + (ES_OFF + c * 256 + k4) * 4,
                 g_cbT + c * 1024 + k4);
        }
        cp_commit();

        cp_wait<1>();                         // xs ready
        __syncthreads();

        // x_sq per spatial row: sequential over c, square-then-add (ref order)
        if (tid < 128) {
            float s = 0.f;
            #pragma unroll
            for (int c = 0; c < 64; ++c) {
                float v = xs[c * 128 + tid];
                s = __fadd_rn(s, __fmul_rn(v, v));
            }
            xsq_sh[tid] = s;
        }

        float minv[8]; int mink[8];
        #pragma unroll
        for (int i = 0; i < 8; ++i) { minv[i] = FLT_MAX; mink[i] = 0; }

        for (int chunk = 0; chunk < N_CHUNKS; ++chunk) {
            const int k0  = chunk * K_CHUNK;
            const int buf = chunk & 1;
            float* eb = smem + ES_OFF + buf * 16384;

            if (chunk + 1 < N_CHUNKS) {       // prefetch next chunk
                int nb = (chunk + 1) & 1;
                int nk0 = k0 + K_CHUNK;
                #pragma unroll
                for (int i = 0; i < 16; ++i) {
                    int lin = i * 256 + tid;
                    int c   = lin >> 6;
                    int k4  = (lin & 63) << 2;
                    cp16(smem_u32 + (ES_OFF + nb * 16384 + c * 256 + k4) * 4,
                         g_cbT + c * 1024 + nk0 + k4);
                }
                cp_commit();
                cp_wait<1>();                 // current buf complete
            } else {
                cp_wait<0>();
            }
            __syncthreads();                  // eb visible to all

            float acc[8][16];
            #pragma unroll
            for (int i = 0; i < 8; ++i)
                #pragma unroll
                for (int j = 0; j < 16; ++j) acc[i][j] = 0.f;

            #pragma unroll 2
            for (int c = 0; c < 64; ++c) {
                float a[8], bb[16];
                *(float4*)(a)     = *(float4*)(xs + c * 128 + tx * 8);
                *(float4*)(a + 4) = *(float4*)(xs + c * 128 + tx * 8 + 4);
                *(float4*)(bb)      = *(float4*)(eb + c * 256 + ty * 16);
                *(float4*)(bb + 4)  = *(float4*)(eb + c * 256 + ty * 16 + 4);
                *(float4*)(bb + 8)  = *(float4*)(eb + c * 256 + ty * 16 + 8);
                *(float4*)(bb + 12) = *(float4*)(eb + c * 256 + ty * 16 + 12);
                #pragma unroll
                for (int i = 0; i < 8; ++i)
                    #pragma unroll
                    for (int j = 0; j < 16; ++j)
                        acc[i][j] = __fmaf_rn(a[i], bb[j], acc[i][j]);
            }

            // Score: d2 = (x_sq + e_sq) - 2*dot. mul-by-2 is exact, so
            // fma(-2, dot, t1) rounds identically to sub(t1, mul(2,dot)).
            float esq[16];
            #pragma unroll
            for (int j = 0; j < 16; ++j)
                esq[j] = __ldg(g_esq + k0 + ty * 16 + j);
            #pragma unroll
            for (int i = 0; i < 8; ++i) {
                float xqv = xsq_sh[tx * 8 + i];
                #pragma unroll
                for (int j = 0; j < 16; ++j) {      // kg ascending: tie->low idx
                    float t1 = __fadd_rn(xqv, esq[j]);
                    float d2 = __fmaf_rn(-2.0f, acc[i][j], t1);
                    if (d2 < minv[i]) { minv[i] = d2; mink[i] = k0 + ty * 16 + j; }
                }
            }
            __syncthreads();   // all done with eb before it is refilled
        }

        // Cross-thread argmin reduction (16 code-groups per spatial row)
        #pragma unroll
        for (int i = 0; i < 8; ++i) {
            rmv[ty * 128 + tx * 8 + i] = minv[i];
            rmk[ty * 128 + tx * 8 + i] = mink[i];
        }
        __syncthreads();
        if (tid < 128) {
            float bv = rmv[tid]; int bk = rmk[tid];
            #pragma unroll
            for (int t = 1; t < 16; ++t) {
                float v = rmv[t * 128 + tid];
                int  k  = rmk[t * 128 + tid];
                if (v < bv || (v == bv && k < bk)) { bv = v; bk = k; }
            }
            idx_sh[tid] = bk;
        }
        __syncthreads();

        // Epilogue: gather codebook rows, write z_q (coalesced per channel),
        // accumulate squared diff deterministically.
        float fsum = 0.f;
        const size_t obase = (size_t)b * 262144 + sb;
        #pragma unroll
        for (int it = 0; it < 32; ++it) {
            int lin = it * 256 + tid;
            int c   = lin >> 7;
            int s   = lin & 127;
            float q = __ldg(cb + idx_sh[s] * 64 + c);
            out[obase + (size_t)c * 4096 + s] = q;
            float d = xs[c * 128 + s] - q;
            fsum = __fmaf_rn(d, d, fsum);
        }
        __syncthreads();
        rmv[tid] = fsum;
        __syncthreads();
        for (int off = 128; off > 0; off >>= 1) {
            if (tid < off) rmv[tid] = __fadd_rn(rmv[tid], rmv[tid + off]);
            __syncthreads();
        }
        if (tid == 0) g_part[tileId] = (double)rmv[0];
        // loop-top __syncthreads fences smem reuse before next tile
    }
}

__global__ void vq_loss(float* loss_out) {
    __shared__ double sh[256];
    double s = 0.0;
    for (int i = threadIdx.x; i < NTILES; i += 256) s += g_part[i];
    sh[threadIdx.x] = s;
    __syncthreads();
    for (int off = 128; off > 0; off >>= 1) {
        if (threadIdx.x < off) sh[threadIdx.x] += sh[threadIdx.x + off];
        __syncthreads();
    }
    if (threadIdx.x == 0) {
        float m = (float)(sh[0] / 8388608.0);
        loss_out[0] = __fadd_rn(m, __fmul_rn(0.25f, m));  // mse + 0.25*mse
    }
}

extern "C" void kernel_launch(void* const* d_in, const int* in_sizes, int n_in,
                              void* d_out, int out_size) {
    const float* x  = (const float*)d_in[0];
    const float* cb = (const float*)d_in[1];
    float* out = (float*)d_out;

    cudaFuncSetAttribute(vq_main, cudaFuncAttributeMaxDynamicSharedMemorySize,
                         SMEM_BYTES);
    vq_prep<<<256, 256>>>(cb);
    vq_main<<<GRID_MAIN, 256, SMEM_BYTES>>>(x, cb, out);
    vq_loss<<<1, 256>>>(out + (out_size - 1));
}

// round 7
// speedup vs baseline: 1.3089x; 1.2889x over previous
#include <cuda_runtime.h>
#include <cuda_bf16.h>
#include <float.h>

#define NTILES    1024
#define GRID_MAIN 304
#define MARGIN    1.25e-4f

// ---- smem layout (bytes); rows padded to 144B (72 bf16) for ldmatrix ----
#define OFF_XH   0        // 128 x 144B  x-hi
#define OFF_XL   18432    // 128 x 144B  x-lo
#define OFF_EH   36864    // 128 x 144B  codebook-hi chunk
#define OFF_EL   55296    // 128 x 144B  codebook-lo chunk
#define OFF_ESQ  73728    // 1024 f32
#define OFF_CTRL 77824    // s_tile
#define SMEM_MAIN 77952

__device__ float          g_cbT[64 * 1024];     // [c][k] fp32 (exact rescore)
__device__ float          g_esq[1024];
__device__ __nv_bfloat16  g_cbh[1024 * 64];     // [k][c] hi
__device__ __nv_bfloat16  g_cbl[1024 * 64];     // [k][c] lo
__device__ int            g_idx_arr[131072];
__device__ int            g_flag_rows[131072];
__device__ int            g_flag_cnt, g_tile, g_resc;
__device__ double         g_part[NTILES];

// ---------------- helpers ----------------
__device__ __forceinline__ unsigned su32(const void* p) {
    return (unsigned)__cvta_generic_to_shared(p);
}
__device__ __forceinline__ void cp16(unsigned dst, const void* src) {
    asm volatile("cp.async.cg.shared.global [%0], [%1], 16;" :: "r"(dst), "l"(src));
}
__device__ __forceinline__ void cp_commit() { asm volatile("cp.async.commit_group;"); }
template <int N> __device__ __forceinline__ void cp_wait() {
    asm volatile("cp.async.wait_group %0;" :: "n"(N));
}
__device__ __forceinline__ void ldm4(unsigned* r, unsigned addr) {
    asm volatile("ldmatrix.sync.aligned.m8n8.x4.shared.b16 {%0,%1,%2,%3}, [%4];"
                 : "=r"(r[0]), "=r"(r[1]), "=r"(r[2]), "=r"(r[3]) : "r"(addr));
}
__device__ __forceinline__ void mma16816(float* c, const unsigned* a, const unsigned* b) {
    asm volatile(
        "mma.sync.aligned.m16n8k16.row.col.f32.bf16.bf16.f32 "
        "{%0,%1,%2,%3}, {%4,%5,%6,%7}, {%8,%9}, {%0,%1,%2,%3};"
        : "+f"(c[0]), "+f"(c[1]), "+f"(c[2]), "+f"(c[3])
        : "r"(a[0]), "r"(a[1]), "r"(a[2]), "r"(a[3]), "r"(b[0]), "r"(b[1]));
}
__device__ __forceinline__ void upd(float& m1, float& m2, int& idx, float sc, int k) {
    m2 = fminf(m2, fmaxf(m1, sc));
    if (sc < m1) { m1 = sc; idx = k; }
}

// ---------------- prep ----------------
__global__ void vq_prep(const float* __restrict__ cb) {
    int o = blockIdx.x * 256 + threadIdx.x;
    if (o == 0) { g_tile = 0; g_flag_cnt = 0; g_resc = 0; }
    if (o < 65536) {
        float v = cb[o];                       // o = k*64 + c
        __nv_bfloat16 h = __float2bfloat16_rn(v);
        g_cbh[o] = h;
        g_cbl[o] = __float2bfloat16_rn(v - __bfloat162float(h));
        int k = o >> 6, c = o & 63;
        g_cbT[c * 1024 + k] = v;
    }
    if (o < 1024) {
        const float* row = cb + o * 64;
        float s = 0.f;
        #pragma unroll
        for (int c = 0; c < 64; ++c) s = __fadd_rn(s, __fmul_rn(row[c], row[c]));
        g_esq[o] = s;
    }
}

// ---------------- main: HMMA phase-1 argmin ----------------
__global__ void __launch_bounds__(256, 2)
vq_main(const float* __restrict__ x) {
    extern __shared__ char sm[];
    const unsigned sb32 = su32(sm);
    float* esq_sh = (float*)(sm + OFF_ESQ);
    int*   ctrl   = (int*)(sm + OFF_CTRL);

    const int tid  = threadIdx.x;
    const int wid  = tid >> 5;
    const int lane = tid & 31;
    const int rs   = lane & 7;
    const int g1   = (lane >> 3) & 1;
    const int g2   = (lane >> 4) & 1;
    const int qp   = lane & 3;          // quad position (col pair)
    const int qr   = lane >> 2;         // row within warp half

    // ldmatrix per-thread byte offsets
    // A matrices: m0(r,k0) m1(r+8,k0) m2(r,k0+8) m3(r+8,k0+8)
    const unsigned aoff = (unsigned)((wid * 16 + rs + g1 * 8) * 144 + g2 * 16);
    // B matrices: m0(n,k0) m1(n,k0+8) m2(n+8,k0) m3(n+8,k0+8)
    const unsigned boff = (unsigned)((rs + g2 * 8) * 144 + g1 * 16);

    for (int i = tid; i < 1024; i += 256) esq_sh[i] = g_esq[i];

    while (true) {
        if (tid == 0) ctrl[0] = atomicAdd(&g_tile, 1);
        __syncthreads();
        const int tile = ctrl[0];
        if (tile >= NTILES) return;
        const int b  = tile >> 5;
        const int sp = (tile & 31) * 128;
        const float* xbase = x + (size_t)b * 262144 + sp;

        // ---- convert x -> xh/xl bf16, [s][c] stride 72 bf16 ----
        {
            const int s = tid >> 1, ch0 = (tid & 1) * 32;
            char* ph = sm + OFF_XH + s * 144 + ch0 * 2;
            char* pl = sm + OFF_XL + s * 144 + ch0 * 2;
            #pragma unroll
            for (int c = 0; c < 32; c += 2) {
                float v0 = __ldg(xbase + (size_t)(ch0 + c) * 4096 + s);
                float v1 = __ldg(xbase + (size_t)(ch0 + c + 1) * 4096 + s);
                __nv_bfloat162 h2 = __floats2bfloat162_rn(v0, v1);
                float l0 = v0 - __bfloat162float(h2.x);
                float l1 = v1 - __bfloat162float(h2.y);
                __nv_bfloat162 l2 = __floats2bfloat162_rn(l0, l1);
                *(unsigned*)(ph + c * 2) = *(unsigned*)&h2;
                *(unsigned*)(pl + c * 2) = *(unsigned*)&l2;
            }
        }

        // ---- kick codebook chunk 0 ----
        #pragma unroll
        for (int i = 0; i < 4; ++i) {
            int lin = i * 256 + tid;             // 1024: k = lin>>3, part = lin&7
            int k = lin >> 3, part = lin & 7;
            cp16(sb32 + OFF_EH + k * 144 + part * 16,
                 (const char*)g_cbh + (size_t)(k * 64 + part * 8) * 2);
            cp16(sb32 + OFF_EL + k * 144 + part * 16,
                 (const char*)g_cbl + (size_t)(k * 64 + part * 8) * 2);
        }
        cp_commit();

        float m1A = FLT_MAX, m2A = FLT_MAX, m1B = FLT_MAX, m2B = FLT_MAX;
        int   iA = 0, iB = 0;

        for (int chunk = 0; chunk < 8; ++chunk) {
            cp_wait<0>();
            __syncthreads();     // eh/el ready; xh/xl stores visible (chunk 0)

            float acc[16][4];
            #pragma unroll
            for (int s16 = 0; s16 < 16; ++s16)
                #pragma unroll
                for (int q = 0; q < 4; ++q) acc[s16][q] = 0.f;

            #pragma unroll
            for (int ks = 0; ks < 4; ++ks) {
                unsigned ah[4], al[4];
                ldm4(ah, sb32 + OFF_XH + aoff + ks * 32);
                ldm4(al, sb32 + OFF_XL + aoff + ks * 32);
                #pragma unroll
                for (int np = 0; np < 8; ++np) {
                    unsigned bh[4], bl[4];
                    unsigned ba = boff + np * (16 * 144) + ks * 32;
                    ldm4(bh, sb32 + OFF_EH + ba);
                    ldm4(bl, sb32 + OFF_EL + ba);
                    mma16816(acc[np * 2],     ah, bh);
                    mma16816(acc[np * 2],     ah, bl);
                    mma16816(acc[np * 2],     al, bh);
                    mma16816(acc[np * 2 + 1], ah, bh + 2);
                    mma16816(acc[np * 2 + 1], ah, bl + 2);
                    mma16816(acc[np * 2 + 1], al, bh + 2);
                }
            }
            __syncthreads();     // all warps done reading eh/el

            if (chunk < 7) {     // prefetch next chunk; scoring hides latency
                const char* gh = (const char*)g_cbh + (size_t)(chunk + 1) * 8192 * 2;
                const char* gl = (const char*)g_cbl + (size_t)(chunk + 1) * 8192 * 2;
                #pragma unroll
                for (int i = 0; i < 4; ++i) {
                    int lin = i * 256 + tid;
                    int k = lin >> 3, part = lin & 7;
                    cp16(sb32 + OFF_EH + k * 144 + part * 16, gh + (k * 64 + part * 8) * 2);
                    cp16(sb32 + OFF_EL + k * 144 + part * 16, gl + (k * 64 + part * 8) * 2);
                }
                cp_commit();
            }

            // ---- score this chunk from register fragments ----
            const int cbase = chunk * 128;
            #pragma unroll
            for (int s16 = 0; s16 < 16; ++s16) {
                const int col = cbase + s16 * 8 + qp * 2;
                float2 eq = *(float2*)(esq_sh + col);
                upd(m1A, m2A, iA, __fmaf_rn(-2.f, acc[s16][0], eq.x), col);
                upd(m1A, m2A, iA, __fmaf_rn(-2.f, acc[s16][1], eq.y), col + 1);
                upd(m1B, m2B, iB, __fmaf_rn(-2.f, acc[s16][2], eq.x), col);
                upd(m1B, m2B, iB, __fmaf_rn(-2.f, acc[s16][3], eq.y), col + 1);
            }
        }

        // ---- quad merge (4 threads share each row) ----
        #pragma unroll
        for (int off = 1; off <= 2; off <<= 1) {
            float o1 = __shfl_xor_sync(0xffffffffu, m1A, off);
            float o2 = __shfl_xor_sync(0xffffffffu, m2A, off);
            int   oi = __shfl_xor_sync(0xffffffffu, iA,  off);
            float nm2 = fminf(fminf(m2A, o2), fmaxf(m1A, o1));
            if (o1 < m1A || (o1 == m1A && oi < iA)) { m1A = o1; iA = oi; }
            m2A = nm2;
            o1 = __shfl_xor_sync(0xffffffffu, m1B, off);
            o2 = __shfl_xor_sync(0xffffffffu, m2B, off);
            oi = __shfl_xor_sync(0xffffffffu, iB,  off);
            nm2 = fminf(fminf(m2B, o2), fmaxf(m1B, o1));
            if (o1 < m1B || (o1 == m1B && oi < iB)) { m1B = o1; iB = oi; }
            m2B = nm2;
        }
        if (qp == 0) {
            int rowA = tile * 128 + wid * 16 + qr;
            g_idx_arr[rowA] = iA;
            if (m2A - m1A < MARGIN) g_flag_rows[atomicAdd(&g_flag_cnt, 1)] = rowA;
            int rowB = rowA + 8;
            g_idx_arr[rowB] = iB;
            if (m2B - m1B < MARGIN) g_flag_rows[atomicAdd(&g_flag_cnt, 1)] = rowB;
        }
        __syncthreads();   // xh/xl reuse fence for next tile
    }
}

// ---------------- exact rescore of flagged rows (warp per row) ----------------
__global__ void __launch_bounds__(256, 2)
vq_rescore(const float* __restrict__ x) {
    __shared__ float xrow[8][64];
    __shared__ int   grab[8];
    const int w = threadIdx.x >> 5, lane = threadIdx.x & 31;
    const int nflag = g_flag_cnt;

    while (true) {
        if (lane == 0) grab[w] = atomicAdd(&g_resc, 1);
        __syncwarp();
        int i = grab[w];
        if (i >= nflag) return;
        int row = g_flag_rows[i];
        int b = row >> 12, s = row & 4095;

        xrow[w][lane]      = __ldg(x + (size_t)b * 262144 + (size_t)lane * 4096 + s);
        xrow[w][lane + 32] = __ldg(x + (size_t)b * 262144 + (size_t)(lane + 32) * 4096 + s);
        __syncwarp();

        float xsq = 0.f;
        #pragma unroll
        for (int c = 0; c < 64; ++c) {
            float v = xrow[w][c];
            xsq = __fadd_rn(xsq, __fmul_rn(v, v));
        }
        float acc[32];
        #pragma unroll
        for (int i2 = 0; i2 < 32; ++i2) acc[i2] = 0.f;
        #pragma unroll 4
        for (int c = 0; c < 64; ++c) {
            float xv = xrow[w][c];
            const float* p = g_cbT + c * 1024 + lane;
            #pragma unroll
            for (int i2 = 0; i2 < 32; ++i2)
                acc[i2] = __fmaf_rn(xv, __ldg(p + i2 * 32), acc[i2]);
        }
        float bv = FLT_MAX; int bk = 0;
        #pragma unroll
        for (int i2 = 0; i2 < 32; ++i2) {
            int k = i2 * 32 + lane;
            float t1 = __fadd_rn(xsq, __ldg(g_esq + k));
            float d2 = __fsub_rn(t1, __fmul_rn(2.f, acc[i2]));
            if (d2 < bv || (d2 == bv && k < bk)) { bv = d2; bk = k; }
        }
        #pragma unroll
        for (int off = 16; off > 0; off >>= 1) {
            float ov = __shfl_xor_sync(0xffffffffu, bv, off);
            int   ok = __shfl_xor_sync(0xffffffffu, bk, off);
            if (ov < bv || (ov == bv && ok < bk)) { bv = ov; bk = ok; }
        }
        if (lane == 0) g_idx_arr[row] = bk;
        __syncwarp();
    }
}

// ---------------- gather z_q + deterministic mse partials ----------------
__global__ void vq_gather(const float* __restrict__ x, const float* __restrict__ cb,
                          float* __restrict__ out) {
    __shared__ int idx_sh[128];
    __shared__ float red[256];
    const int tid = threadIdx.x, tile = blockIdx.x;
    const int b = tile >> 5, sp = (tile & 31) * 128;
    if (tid < 128) idx_sh[tid] = g_idx_arr[tile * 128 + tid];
    __syncthreads();

    float fsum = 0.f;
    const size_t base = (size_t)b * 262144 + sp;
    #pragma unroll
    for (int it = 0; it < 32; ++it) {
        int lin = it * 256 + tid;
        int c = lin >> 7, s = lin & 127;
        float q  = __ldg(cb + idx_sh[s] * 64 + c);
        float xv = __ldg(x + base + (size_t)c * 4096 + s);
        out[base + (size_t)c * 4096 + s] = q;
        float d = xv - q;
        fsum = __fmaf_rn(d, d, fsum);
    }
    red[tid] = fsum;
    __syncthreads();
    for (int off = 128; off > 0; off >>= 1) {
        if (tid < off) red[tid] = __fadd_rn(red[tid], red[tid + off]);
        __syncthreads();
    }
    if (tid == 0) g_part[tile] = (double)red[0];
}

__global__ void vq_loss(float* loss_out) {
    __shared__ double sh[256];
    double s = 0.0;
    for (int i = threadIdx.x; i < NTILES; i += 256) s += g_part[i];
    sh[threadIdx.x] = s;
    __syncthreads();
    for (int off = 128; off > 0; off >>= 1) {
        if (threadIdx.x < off) sh[threadIdx.x] += sh[threadIdx.x + off];
        __syncthreads();
    }
    if (threadIdx.x == 0) {
        float m = (float)(sh[0] / 8388608.0);
        loss_out[0] = __fadd_rn(m, __fmul_rn(0.25f, m));
    }
}

extern "C" void kernel_launch(void* const* d_in, const int* in_sizes, int n_in,
                              void* d_out, int out_size) {
    const float* x  = (const float*)d_in[0];
    const float* cb = (const float*)d_in[1];
    float* out = (float*)d_out;

    cudaFuncSetAttribute(vq_main, cudaFuncAttributeMaxDynamicSharedMemorySize, SMEM_MAIN);
    vq_prep<<<256, 256>>>(cb);
    vq_main<<<GRID_MAIN, 256, SMEM_MAIN>>>(x);
    vq_rescore<<<152, 256>>>(x);
    vq_gather<<<NTILES, 256>>>(x, cb, out);
    vq_loss<<<1, 256>>>(out + (out_size - 1));
}